// round 17
// baseline (speedup 1.0000x reference)
#include <cuda_runtime.h>
#include <cstdint>

// ---------------------------------------------------------------------------
// CurveChannel — FINAL, converged (timed 8.639/8.672/8.704us over three
// independent benches; best mean and best min of all 11 structures tested).
//
// Session model (16 rounds): cold-stream reads cap at ~3 TB/s on this GB300,
// metered by the L2-miss outstanding-transaction budget (~1.1MB chip-wide =
// BW x ~380ns DRAM latency). DRAM sits ~37% active; every SM-side metric is
// idle. Invariant across LDG/TMA/dual-path issue, occupancy 32-80%, MLP
// 1-12, and 0.8-24MB demanded in flight. Irreducible traffic (25.2MB read +
// 8.4MB write) -> ~8.0us kernel floor + ~0.6us graph-replay overhead.
//
// Kernel: barrier-free, no shared memory. conv_w folded into slopes; nonzero
// breakpoints compacted per-warp via ballot+shfl (exact for arbitrary
// slopes; 1 active point/channel in this dataset). Three front-batched
// independent 256-bit loads per thread (ld.global.nc.v8.b32, evict_last),
// fused 1x1 conv + hardtanh, two streaming v4 stores.
// ---------------------------------------------------------------------------

#define NPTS   16
#define IN_CH  3
#define HW8    (512 * 512 / 8)   // 8-float groups per (b,c) plane = 32768
#define TPB    256

struct f8 { float4 a, b; };

__device__ __forceinline__ f8 ldg_evl_256(const void* p) {
    uint32_t r0,r1,r2,r3,r4,r5,r6,r7;
    asm volatile("ld.global.nc.L2::evict_last.v8.b32 "
                 "{%0,%1,%2,%3,%4,%5,%6,%7}, [%8];"
                 : "=r"(r0),"=r"(r1),"=r"(r2),"=r"(r3),
                   "=r"(r4),"=r"(r5),"=r"(r6),"=r"(r7)
                 : "l"(p));
    f8 v;
    v.a.x = __uint_as_float(r0); v.a.y = __uint_as_float(r1);
    v.a.z = __uint_as_float(r2); v.a.w = __uint_as_float(r3);
    v.b.x = __uint_as_float(r4); v.b.y = __uint_as_float(r5);
    v.b.z = __uint_as_float(r6); v.b.w = __uint_as_float(r7);
    return v;
}

__device__ __forceinline__ void stg_cs(float4* p, float4 v) {
    asm volatile("st.global.cs.v4.f32 [%0], {%1,%2,%3,%4};"
                 :: "l"(p), "f"(v.x), "f"(v.y), "f"(v.z), "f"(v.w)
                 : "memory");
}

__global__ __launch_bounds__(TPB) void curve_fused(
    const float* __restrict__ x,       // (8, 3, 512, 512)
    const float* __restrict__ shift,   // (NPTS, C)
    const float* __restrict__ slopes,  // (NPTS, C)
    const float* __restrict__ conv_w,  // (C,)
    const float* __restrict__ conv_b,  // (1,)
    float* __restrict__ out)           // (8, 1, 512, 512)
{
    const int tid  = threadIdx.x;
    const int lane = tid & 31;

    // ---- param loads first (few cache lines, warp-coalesced) ----
    const bool pl = (lane < NPTS);
    float sl0 = pl ? __ldg(&slopes[lane * IN_CH + 0]) : 0.0f;
    float sl1 = pl ? __ldg(&slopes[lane * IN_CH + 1]) : 0.0f;
    float sl2 = pl ? __ldg(&slopes[lane * IN_CH + 2]) : 0.0f;
    float sh0 = pl ? __ldg(&shift [lane * IN_CH + 0]) : 0.0f;
    float sh1 = pl ? __ldg(&shift [lane * IN_CH + 1]) : 0.0f;
    float sh2 = pl ? __ldg(&shift [lane * IN_CH + 2]) : 0.0f;
    const float w0   = __ldg(&conv_w[0]);
    const float w1   = __ldg(&conv_w[1]);
    const float w2   = __ldg(&conv_w[2]);
    const float bias = __ldg(&conv_b[0]);

    // ---- front-batch three independent 256-bit x loads ----
    const int g = blockIdx.x * TPB + tid;     // [0, 8*HW8)
    const int b = g >> 15;                    // g / HW8
    const int v = g & (HW8 - 1);              // g % HW8
    const float* xb = x + (size_t)b * (IN_CH * HW8 * 8) + (size_t)v * 8;

    f8 xv0 = ldg_evl_256(xb + 0 * HW8 * 8);
    f8 xv1 = ldg_evl_256(xb + 1 * HW8 * 8);
    f8 xv2 = ldg_evl_256(xb + 2 * HW8 * 8);

    // ---- active-point masks (overlaps x-load latency) ----
    unsigned m0 = __ballot_sync(0xFFFFFFFFu, sl0 != 0.0f);
    unsigned m1 = __ballot_sync(0xFFFFFFFFu, sl1 != 0.0f);
    unsigned m2 = __ballot_sync(0xFFFFFFFFu, sl2 != 0.0f);

    float4 accA = make_float4(bias, bias, bias, bias);
    float4 accB = make_float4(bias, bias, bias, bias);

    while (m0) {
        int src = __ffs(m0) - 1; m0 &= m0 - 1;
        float sh = __shfl_sync(0xFFFFFFFFu, sh0, src);
        float ws = __shfl_sync(0xFFFFFFFFu, sl0, src) * w0;
        accA.x = fmaf(ws, fmaxf(xv0.a.x - sh, 0.0f), accA.x);
        accA.y = fmaf(ws, fmaxf(xv0.a.y - sh, 0.0f), accA.y);
        accA.z = fmaf(ws, fmaxf(xv0.a.z - sh, 0.0f), accA.z);
        accA.w = fmaf(ws, fmaxf(xv0.a.w - sh, 0.0f), accA.w);
        accB.x = fmaf(ws, fmaxf(xv0.b.x - sh, 0.0f), accB.x);
        accB.y = fmaf(ws, fmaxf(xv0.b.y - sh, 0.0f), accB.y);
        accB.z = fmaf(ws, fmaxf(xv0.b.z - sh, 0.0f), accB.z);
        accB.w = fmaf(ws, fmaxf(xv0.b.w - sh, 0.0f), accB.w);
    }
    while (m1) {
        int src = __ffs(m1) - 1; m1 &= m1 - 1;
        float sh = __shfl_sync(0xFFFFFFFFu, sh1, src);
        float ws = __shfl_sync(0xFFFFFFFFu, sl1, src) * w1;
        accA.x = fmaf(ws, fmaxf(xv1.a.x - sh, 0.0f), accA.x);
        accA.y = fmaf(ws, fmaxf(xv1.a.y - sh, 0.0f), accA.y);
        accA.z = fmaf(ws, fmaxf(xv1.a.z - sh, 0.0f), accA.z);
        accA.w = fmaf(ws, fmaxf(xv1.a.w - sh, 0.0f), accA.w);
        accB.x = fmaf(ws, fmaxf(xv1.b.x - sh, 0.0f), accB.x);
        accB.y = fmaf(ws, fmaxf(xv1.b.y - sh, 0.0f), accB.y);
        accB.z = fmaf(ws, fmaxf(xv1.b.z - sh, 0.0f), accB.z);
        accB.w = fmaf(ws, fmaxf(xv1.b.w - sh, 0.0f), accB.w);
    }
    while (m2) {
        int src = __ffs(m2) - 1; m2 &= m2 - 1;
        float sh = __shfl_sync(0xFFFFFFFFu, sh2, src);
        float ws = __shfl_sync(0xFFFFFFFFu, sl2, src) * w2;
        accA.x = fmaf(ws, fmaxf(xv2.a.x - sh, 0.0f), accA.x);
        accA.y = fmaf(ws, fmaxf(xv2.a.y - sh, 0.0f), accA.y);
        accA.z = fmaf(ws, fmaxf(xv2.a.z - sh, 0.0f), accA.z);
        accA.w = fmaf(ws, fmaxf(xv2.a.w - sh, 0.0f), accA.w);
        accB.x = fmaf(ws, fmaxf(xv2.b.x - sh, 0.0f), accB.x);
        accB.y = fmaf(ws, fmaxf(xv2.b.y - sh, 0.0f), accB.y);
        accB.z = fmaf(ws, fmaxf(xv2.b.z - sh, 0.0f), accB.z);
        accB.w = fmaf(ws, fmaxf(xv2.b.w - sh, 0.0f), accB.w);
    }

    accA.x = fminf(fmaxf(accA.x, 0.0f), 1.0f);
    accA.y = fminf(fmaxf(accA.y, 0.0f), 1.0f);
    accA.z = fminf(fmaxf(accA.z, 0.0f), 1.0f);
    accA.w = fminf(fmaxf(accA.w, 0.0f), 1.0f);
    accB.x = fminf(fmaxf(accB.x, 0.0f), 1.0f);
    accB.y = fminf(fmaxf(accB.y, 0.0f), 1.0f);
    accB.z = fminf(fmaxf(accB.z, 0.0f), 1.0f);
    accB.w = fminf(fmaxf(accB.w, 0.0f), 1.0f);

    float4* op = reinterpret_cast<float4*>(out + (size_t)g * 8);
    stg_cs(op,     accA);
    stg_cs(op + 1, accB);
}

extern "C" void kernel_launch(void* const* d_in, const int* in_sizes, int n_in,
                              void* d_out, int out_size)
{
    const float* x      = (const float*)d_in[0];
    const float* shift  = (const float*)d_in[1];
    const float* slopes = (const float*)d_in[2];
    const float* conv_w = (const float*)d_in[3];
    const float* conv_b = (const float*)d_in[4];
    float* out = (float*)d_out;

    const int total_groups = out_size / 8;    // 262144
    const int blocks = total_groups / TPB;    // 1024
    curve_fused<<<blocks, TPB>>>(x, shift, slopes, conv_w, conv_b, out);
}